// round 17
// baseline (speedup 1.0000x reference)
#include <cuda_runtime.h>
#include <cuda_fp16.h>
#include <stdint.h>

// PatchAttention R17: Q,K,V,O all folded.
//   softmax input = (P·M)P^T + 1·v^T,  M = Wq^T Wk · log2e/tau,  v = P·h,
//   h = Wk^T bq · log2e/tau;   out = x + (exp(.)@P)/rowsum @ Wz^T + bz,
//   Wz = Wo@Wv, bz = Wo@bv + bo.  (u·1^T and const terms cancel in softmax.)
// One CTA/patch (2048 x 256 thr, 8 warps x 32 rows), f16 mma accum,
// pipelined attention, ex2.approx.f16x2 softmax. mma/warp: 1536.

#define SMEM_P     0u        // raw patch P [256][128] f16 swizzled (64 KB)
#define SMEM_W0    65536u    // M stage (32 KB)
#define VBUF       98304u    // v[256] f16 (512 B)
#define SMEM_W1    133120u   // Wz stage (32 KB), above zsf overlay
#define SMEM_Z     0u        // Z [128][260] f32 overlay (133120 B)
#define SMEM_TOTAL 165888u

#define QSCALE ((float)(1.4426950408889634 / 11.313708498984761))  // log2e/sqrt(128)

__device__ uint32_t gW[2][8192];   // f16x2 swizzled: M^T(d,c), Wz
__device__ uint32_t gH2[64];       // f16x2 channel-pair h
__device__ float    gMtF[16384];   // fp32 M^T: [d][c] = sum_k Wq[k,c] Wk[k,d] * QSCALE
__device__ float    gWzF[16384];   // fp32 Wz = Wo @ Wv
__device__ float    gHF[128];      // fp32 h = Wk^T bq * QSCALE
__device__ float    gBz[128];      // fp32 bz = Wo @ bv + bo

__device__ __forceinline__ uint32_t pack2h(float lo, float hi) {
    uint32_t r;
    asm("cvt.rn.f16x2.f32 %0, %1, %2;" : "=r"(r) : "f"(hi), "f"(lo));
    return r;
}
__device__ __forceinline__ float2 up2h(uint32_t u) {
    __half2 h = *reinterpret_cast<__half2*>(&u);
    return __half22float2(h);
}
__device__ __forceinline__ uint16_t h16(float v) {
    uint16_t r;
    asm("cvt.rn.f16.f32 %0, %1;" : "=h"(r) : "f"(v));
    return r;
}
__device__ __forceinline__ uint32_t hadd2u(uint32_t a, uint32_t b) {
    uint32_t d; asm("add.rn.f16x2 %0, %1, %2;" : "=r"(d) : "r"(a), "r"(b)); return d;
}
__device__ __forceinline__ uint32_t hmul2u(uint32_t a, uint32_t b) {
    uint32_t d; asm("mul.rn.f16x2 %0, %1, %2;" : "=r"(d) : "r"(a), "r"(b)); return d;
}
__device__ __forceinline__ uint32_t hfma2u(uint32_t a, uint32_t b, uint32_t c) {
    uint32_t d;
    asm("fma.rn.f16x2 %0, %1, %2, %3;" : "=r"(d) : "r"(a), "r"(b), "r"(c));
    return d;
}
__device__ __forceinline__ uint32_t ex2u(uint32_t a) {
    uint32_t d; asm("ex2.approx.f16x2 %0, %1;" : "=r"(d) : "r"(a)); return d;
}
__device__ __forceinline__ uint32_t mrow(uint32_t base, int row, int chunk) {
    return base + (uint32_t)row * 256u + (uint32_t)(((chunk ^ (row & 7)) << 4));
}
__device__ __forceinline__ void ldsm_x4(uint32_t a, uint32_t r[4]) {
    asm volatile("ldmatrix.sync.aligned.m8n8.x4.shared.b16 {%0,%1,%2,%3}, [%4];"
                 : "=r"(r[0]), "=r"(r[1]), "=r"(r[2]), "=r"(r[3]) : "r"(a));
}
__device__ __forceinline__ void ldsm_x4t(uint32_t a, uint32_t r[4]) {
    asm volatile("ldmatrix.sync.aligned.m8n8.x4.trans.shared.b16 {%0,%1,%2,%3}, [%4];"
                 : "=r"(r[0]), "=r"(r[1]), "=r"(r[2]), "=r"(r[3]) : "r"(a));
}
__device__ __forceinline__ void mma_h(uint32_t c[2], const uint32_t a[4],
                                      uint32_t b0, uint32_t b1) {
    asm volatile(
        "mma.sync.aligned.m16n8k16.row.col.f16.f16.f16.f16 "
        "{%0,%1},{%2,%3,%4,%5},{%6,%7},{%0,%1};"
        : "+r"(c[0]), "+r"(c[1])
        : "r"(a[0]), "r"(a[1]), "r"(a[2]), "r"(a[3]), "r"(b0), "r"(b1));
}
__device__ __forceinline__ void cp16(uint32_t s, const void* g) {
    asm volatile("cp.async.ca.shared.global [%0], [%1], 16;" :: "r"(s), "l"(g));
}
__device__ __forceinline__ void cp_commit() { asm volatile("cp.async.commit_group;"); }
__device__ __forceinline__ void cp_wait_all() { asm volatile("cp.async.wait_group 0;"); }

// ---- prep 1: M^T, Wz, h, bz (fp32, 4-way ILP) -------------------------------
__global__ void prep_fold(const float* __restrict__ Wq, const float* __restrict__ Wk,
                          const float* __restrict__ Wv, const float* __restrict__ Wo,
                          const float* __restrict__ bq, const float* __restrict__ bv,
                          const float* __restrict__ bo) {
    int i = blockIdx.x, j = threadIdx.x;   // 128 x 128
    float m0 = 0.f, m1 = 0.f, m2 = 0.f, m3 = 0.f;
    float z0 = 0.f, z1 = 0.f, z2 = 0.f, z3 = 0.f;
#pragma unroll 4
    for (int k = 0; k < 128; k += 4) {
        m0 = fmaf(Wq[(k+0)*128 + j], Wk[(k+0)*128 + i], m0);
        m1 = fmaf(Wq[(k+1)*128 + j], Wk[(k+1)*128 + i], m1);
        m2 = fmaf(Wq[(k+2)*128 + j], Wk[(k+2)*128 + i], m2);
        m3 = fmaf(Wq[(k+3)*128 + j], Wk[(k+3)*128 + i], m3);
        z0 = fmaf(Wo[i*128 + k+0], Wv[(k+0)*128 + j], z0);
        z1 = fmaf(Wo[i*128 + k+1], Wv[(k+1)*128 + j], z1);
        z2 = fmaf(Wo[i*128 + k+2], Wv[(k+2)*128 + j], z2);
        z3 = fmaf(Wo[i*128 + k+3], Wv[(k+3)*128 + j], z3);
    }
    gMtF[i*128 + j] = ((m0 + m1) + (m2 + m3)) * QSCALE;
    gWzF[i*128 + j] = (z0 + z1) + (z2 + z3);
    if (i == 0) {   // h[j] = sum_d Wk[d,j] * bq[d]
        float h0 = 0.f, h1 = 0.f;
        for (int d = 0; d < 128; d += 2) {
            h0 = fmaf(Wk[(d+0)*128 + j], bq[d+0], h0);
            h1 = fmaf(Wk[(d+1)*128 + j], bq[d+1], h1);
        }
        gHF[j] = (h0 + h1) * QSCALE;
    }
    if (j == 0) {   // bz[i] = bo[i] + sum_k Wo[i,k] * bv[k]
        float b0 = 0.f, b1 = 0.f;
        for (int k = 0; k < 128; k += 2) {
            b0 = fmaf(Wo[i*128 + k+0], bv[k+0], b0);
            b1 = fmaf(Wo[i*128 + k+1], bv[k+1], b1);
        }
        gBz[i] = bo[i] + b0 + b1;
    }
}

// ---- prep 2: pack M^T, Wz -> f16x2 swizzled; h -> f16x2 pairs ---------------
__global__ void prep_pack() {
    int t = blockIdx.x * 256 + threadIdx.x;  // 8192 threads
    int d = t >> 6, j = t & 63;
    uint32_t slot = (uint32_t)(d * 64 + (((j >> 2) ^ (d & 7)) << 2) + (j & 3));
    gW[0][slot] = pack2h(gMtF[d*128 + 2*j], gMtF[d*128 + 2*j + 1]);
    gW[1][slot] = pack2h(gWzF[d*128 + 2*j], gWzF[d*128 + 2*j + 1]);
    if (t < 64) gH2[t] = pack2h(gHF[2*t], gHF[2*t + 1]);
}

__global__ void __launch_bounds__(256, 1)
PatchAttention_24902220382269_kernel(
    const float* __restrict__ x, float* __restrict__ out)
{
    extern __shared__ char smem[];
    const uint32_t sb = (uint32_t)__cvta_generic_to_shared(smem);
    const int tid  = threadIdx.x;
    const int lane = tid & 31;
    const int warp = tid >> 5;
    const int tm   = warp * 32;

    const int pid   = blockIdx.x;
    const int xbase = (pid >> 10) * 33554432 + ((pid >> 5) & 31) * 8192 + (pid & 31) * 16;

    // stage M, Wz (pre-swizzled f16) once
#pragma unroll
    for (int i = 0; i < 8; i++) {
        int ch = tid + i * 256;
        cp16(sb + SMEM_W0 + ch * 16, (const char*)gW[0] + ch * 16);
        cp16(sb + SMEM_W1 + ch * 16, (const char*)gW[1] + ch * 16);
    }
    cp_commit();

    // patch load: x -> P token-major f16 swizzled
#pragma unroll 4
    for (int i = 0; i < 32; i++) {
        int it = tid + i * 256;
        int c = it >> 6, q = it & 63;
        int sh = q >> 2, sw4 = (q & 3) << 2;
        float4 v4 = *reinterpret_cast<const float4*>(
            x + xbase + c * 262144 + sh * 512 + sw4);
        int l = sh * 16 + sw4;
        float vv[4] = {v4.x, v4.y, v4.z, v4.w};
#pragma unroll
        for (int j = 0; j < 4; j++) {
            int row = l + j;
            *reinterpret_cast<uint16_t*>(smem + SMEM_P + (uint32_t)row * 256u +
                (uint32_t)((((c >> 3) ^ (row & 7)) << 4) + (c & 7) * 2)) = h16(vv[j]);
        }
    }
    cp_wait_all();
    __syncthreads();

    const int g = lane >> 2;

    // ---- v = P · h (per-thread f16x2 dot over own token row) ----
    {
        uint32_t acc2 = 0u;
#pragma unroll
        for (int ch = 0; ch < 8; ch++) {
            uint32_t off = (uint32_t)tid * 256u + (uint32_t)(((ch ^ (tid & 7)) << 4));
            uint4 pr = *reinterpret_cast<const uint4*>(smem + SMEM_P + off);
            acc2 = hfma2u(pr.x, __ldg(&gH2[ch*4 + 0]), acc2);
            acc2 = hfma2u(pr.y, __ldg(&gH2[ch*4 + 1]), acc2);
            acc2 = hfma2u(pr.z, __ldg(&gH2[ch*4 + 2]), acc2);
            acc2 = hfma2u(pr.w, __ldg(&gH2[ch*4 + 3]), acc2);
        }
        float2 vv = up2h(acc2);
        *reinterpret_cast<uint16_t*>(smem + VBUF + tid * 2) = h16(vv.x + vv.y);
    }

    // ---- Q' = P · M -> registers (accumulate directly into A-frag slots) ----
    uint32_t qa[2][8][4];
#pragma unroll
    for (int m = 0; m < 2; m++)
#pragma unroll
        for (int kt = 0; kt < 8; kt++)
#pragma unroll
            for (int j = 0; j < 4; j++) qa[m][kt][j] = 0u;
#pragma unroll
    for (int kt = 0; kt < 8; kt++) {
        uint32_t a0[4], a1[4];
        ldsm_x4(mrow(sb + SMEM_P, tm +      (lane & 15), kt * 2 + (lane >> 4)), a0);
        ldsm_x4(mrow(sb + SMEM_P, tm + 16 + (lane & 15), kt * 2 + (lane >> 4)), a1);
#pragma unroll
        for (int np = 0; np < 8; np++) {
            uint32_t wb[4];
            ldsm_x4(mrow(sb + SMEM_W0, np * 16 + (lane & 15),
                         kt * 2 + (lane >> 4)), wb);
            mma_h(&qa[0][np][0], a0, wb[0], wb[2]);
            mma_h(&qa[0][np][2], a0, wb[1], wb[3]);
            mma_h(&qa[1][np][0], a1, wb[0], wb[2]);
            mma_h(&qa[1][np][2], a1, wb[1], wb[3]);
        }
    }
    __syncthreads();   // vbuf visible to all

    // ---- attention (pipelined): T = exp2(Q' P^T + 1 v^T) @ P ----
    uint32_t yacc[2][16][2];
#pragma unroll
    for (int m = 0; m < 2; m++)
#pragma unroll
        for (int nt = 0; nt < 16; nt++) { yacc[m][nt][0] = 0u; yacc[m][nt][1] = 0u; }
    float rs[2][2] = {{0.f, 0.f}, {0.f, 0.f}};

    auto computeS = [&](int k0, uint32_t s[8]) {
#pragma unroll
        for (int i = 0; i < 8; i++) s[i] = 0u;
#pragma unroll
        for (int kt = 0; kt < 8; kt++) {
            uint32_t kb[4];
            ldsm_x4(mrow(sb + SMEM_P, k0 + (lane & 15), kt * 2 + (lane >> 4)), kb);
            mma_h(s + 0, qa[0][kt], kb[0], kb[2]);
            mma_h(s + 2, qa[0][kt], kb[1], kb[3]);
            mma_h(s + 4, qa[1][kt], kb[0], kb[2]);
            mma_h(s + 6, qa[1][kt], kb[1], kb[3]);
        }
    };

    uint32_t scur[8];
    computeS(0, scur);
#pragma unroll 1
    for (int kc = 0; kc < 16; kc++) {
        uint32_t vv0 = *reinterpret_cast<const uint32_t*>(
            smem + VBUF + kc * 32 + (lane & 3) * 4);
        uint32_t vv1 = *reinterpret_cast<const uint32_t*>(
            smem + VBUF + kc * 32 + 16 + (lane & 3) * 4);
        uint32_t pa[2][4];
#pragma unroll
        for (int m = 0; m < 2; m++) {
            pa[m][0] = ex2u(hadd2u(scur[m*4 + 0], vv0));
            pa[m][1] = ex2u(hadd2u(scur[m*4 + 1], vv0));
            pa[m][2] = ex2u(hadd2u(scur[m*4 + 2], vv1));
            pa[m][3] = ex2u(hadd2u(scur[m*4 + 3], vv1));
            float2 t0 = up2h(hadd2u(pa[m][0], pa[m][2]));
            float2 t1 = up2h(hadd2u(pa[m][1], pa[m][3]));
            rs[m][0] += t0.x + t0.y;
            rs[m][1] += t1.x + t1.y;
        }
        uint32_t snxt[8];
        if (kc < 15) computeS((kc + 1) * 16, snxt);
#pragma unroll
        for (int np = 0; np < 8; np++) {
            uint32_t vb[4];
            ldsm_x4t(mrow(sb + SMEM_P, kc * 16 + (lane & 15), np * 2 + (lane >> 4)), vb);
            mma_h(yacc[0][2*np],   pa[0], vb[0], vb[1]);
            mma_h(yacc[0][2*np+1], pa[0], vb[2], vb[3]);
            mma_h(yacc[1][2*np],   pa[1], vb[0], vb[1]);
            mma_h(yacc[1][2*np+1], pa[1], vb[2], vb[3]);
        }
        if (kc < 15) {
#pragma unroll
            for (int i = 0; i < 8; i++) scur[i] = snxt[i];
        }
    }
#pragma unroll
    for (int m = 0; m < 2; m++)
#pragma unroll
        for (int h = 0; h < 2; h++) {
            float v = rs[m][h];
            v += __shfl_xor_sync(0xffffffffu, v, 1);
            v += __shfl_xor_sync(0xffffffffu, v, 2);
            rs[m][h] = 1.f / v;
        }

    // normalize T -> f16 A frags
    uint32_t ya[2][8][4];
#pragma unroll
    for (int m = 0; m < 2; m++) {
        uint32_t rr0 = pack2h(rs[m][0], rs[m][0]);
        uint32_t rr1 = pack2h(rs[m][1], rs[m][1]);
#pragma unroll
        for (int kt = 0; kt < 8; kt++) {
            ya[m][kt][0] = hmul2u(yacc[m][2*kt][0],   rr0);
            ya[m][kt][1] = hmul2u(yacc[m][2*kt][1],   rr1);
            ya[m][kt][2] = hmul2u(yacc[m][2*kt+1][0], rr0);
            ya[m][kt][3] = hmul2u(yacc[m][2*kt+1][1], rr1);
        }
    }
    __syncthreads();     // all P reads done; zsf may overlay P/W0/vbuf

    // ---- Z = (T/rs) @ Wz^T, fp32 staged in SMEM (stride 260) ----
    float* zsf = reinterpret_cast<float*>(smem + SMEM_Z);
    const int c4 = (lane & 3) << 1;
#pragma unroll 1
    for (int np = 0; np < 8; np++) {
        uint32_t z[2][2][2];
#pragma unroll
        for (int m = 0; m < 2; m++)
#pragma unroll
            for (int n = 0; n < 2; n++) { z[m][n][0] = 0u; z[m][n][1] = 0u; }
#pragma unroll
        for (int kt = 0; kt < 8; kt++) {
            uint32_t wb[4];
            ldsm_x4(mrow(sb + SMEM_W1, np * 16 + (lane & 15),
                         kt * 2 + (lane >> 4)), wb);
            mma_h(z[0][0], ya[0][kt], wb[0], wb[2]);
            mma_h(z[0][1], ya[0][kt], wb[1], wb[3]);
            mma_h(z[1][0], ya[1][kt], wb[0], wb[2]);
            mma_h(z[1][1], ya[1][kt], wb[1], wb[3]);
        }
#pragma unroll
        for (int n = 0; n < 2; n++) {
            int c = (2 * np + n) * 8 + c4;
#pragma unroll
            for (int m = 0; m < 2; m++) {
                int r = tm + m * 16 + g;
                float2 lo = up2h(z[m][n][0]);
                float2 hi = up2h(z[m][n][1]);
                zsf[c * 260 + r]           = lo.x;
                zsf[(c + 1) * 260 + r]     = lo.y;
                zsf[c * 260 + r + 8]       = hi.x;
                zsf[(c + 1) * 260 + r + 8] = hi.y;
            }
        }
    }
    __syncthreads();

    // ---- epilogue: out = x + z + bz (exact fp32 residual) ----
#pragma unroll 4
    for (int i = 0; i < 32; i++) {
        int it = tid + i * 256;
        int c = it >> 6, q = it & 63;
        int sh = q >> 2, sw4 = (q & 3) << 2;
        int l = sh * 16 + sw4;
        int ga = xbase + c * 262144 + sh * 512 + sw4;
        float4 xv = *reinterpret_cast<const float4*>(x + ga);
        float4 zv = *reinterpret_cast<const float4*>(zsf + c * 260 + l);
        float bc = __ldg(&gBz[c]);
        float4 ov;
        ov.x = xv.x + zv.x + bc; ov.y = xv.y + zv.y + bc;
        ov.z = xv.z + zv.z + bc; ov.w = xv.w + zv.w + bc;
        *reinterpret_cast<float4*>(out + ga) = ov;
    }
}

extern "C" void kernel_launch(void* const* d_in, const int* in_sizes, int n_in,
                              void* d_out, int out_size) {
    const float* x  = (const float*)d_in[0];
    const float* Wq = (const float*)d_in[1];
    const float* bq = (const float*)d_in[2];
    const float* Wk = (const float*)d_in[3];
    const float* Wv = (const float*)d_in[5];
    const float* bv = (const float*)d_in[6];
    const float* Wo = (const float*)d_in[7];
    const float* bo = (const float*)d_in[8];
    float* out = (float*)d_out;

    prep_fold<<<128, 128>>>(Wq, Wk, Wv, Wo, bq, bv, bo);
    prep_pack<<<32, 256>>>();

    cudaFuncSetAttribute(PatchAttention_24902220382269_kernel,
                         cudaFuncAttributeMaxDynamicSharedMemorySize, SMEM_TOTAL);
    PatchAttention_24902220382269_kernel<<<2048, 256, SMEM_TOTAL>>>(x, out);
}